// round 2
// baseline (speedup 1.0000x reference)
#include <cuda_runtime.h>
#include <cuda_bf16.h>

// ---------------------------------------------------------------------------
// GCN: h1 = relu(Dd^-1/2 A (Ds^-1/2 x) W1 + b1)
//      h2 = relu(Dd^-1/2 A (Ds^-1/2 h1) W2 + b2)
//      hg = mean-pool(h2, graph_id); out = relu(hg Wr1 + br1) Wr2 + br2
// Outputs concatenated: out (64x128) then h2 (100000x128).
// NOTE: edge_index / graph_id are int32 (JAX x64 disabled downcasts int64).
// ---------------------------------------------------------------------------

#define D 128
#define MAX_NODES 100096
#define MAX_FEAT  12812288   // MAX_NODES * 128

// scratch (device globals: allocation-free rule)
__device__ float g_deg[2 * MAX_NODES];            // deg_out, deg_in
__device__ float g_norm[2 * MAX_NODES];           // norm_src, norm_dst
__device__ float g_t[MAX_FEAT];                   // GEMM output (reused both layers)
__device__ float g_agg[2 * (size_t)MAX_FEAT];     // agg1, agg2
__device__ float g_hg[64 * D];
__device__ float g_tmp[64 * D];

// ---------------------------------------------------------------------------
__global__ void deg_kernel(const int* __restrict__ src,
                           const int* __restrict__ dst,
                           float* __restrict__ dout, float* __restrict__ din,
                           int nE) {
    int e = blockIdx.x * blockDim.x + threadIdx.x;
    if (e < nE) {
        atomicAdd(&dout[src[e]], 1.0f);
        atomicAdd(&din[dst[e]], 1.0f);
    }
}

__global__ void norm_kernel(const float* __restrict__ dout,
                            const float* __restrict__ din,
                            float* __restrict__ ns, float* __restrict__ nd,
                            int n) {
    int i = blockIdx.x * blockDim.x + threadIdx.x;
    if (i < n) {
        ns[i] = rsqrtf(fmaxf(dout[i], 1.0f));
        nd[i] = rsqrtf(fmaxf(din[i], 1.0f));
    }
}

// ---------------------------------------------------------------------------
// Fused GEMM: Y[r] = f(X[r]) @ W, K = N = 128 fixed.
// mode 0: f(x)[k] = x[k] * nsrc[r]
// mode 1: f(x)[k] = relu(x[k]*ndst[r] + bias[k]) * nsrc[r]
// Block: 256 threads, 64 rows x 128 cols. W fully resident in smem.
// ---------------------------------------------------------------------------
__global__ __launch_bounds__(256, 1) void gemm_fused(
    const float* __restrict__ X, const float* __restrict__ W,
    const float* __restrict__ bias, const float* __restrict__ nsrc,
    const float* __restrict__ ndst, float* __restrict__ Y,
    int nRows, int mode)
{
    extern __shared__ float sm[];
    float* Ws = sm;                 // 128*128
    float* Xs = sm + D * D;         // 64*132 (pad 132 kills stride-128 conflicts)
    const int tid = threadIdx.x;
    const int row0 = blockIdx.x * 64;

    // load W: 4096 float4
    {
        const float4* Wg = (const float4*)W;
        float4* Wsm = (float4*)Ws;
#pragma unroll
        for (int i = 0; i < 16; i++) Wsm[tid + i * 256] = Wg[tid + i * 256];
    }
    // load + transform X tile: 64 rows x 32 float4
    {
#pragma unroll
        for (int i = 0; i < 8; i++) {
            int linear = tid + i * 256;     // 0..2047
            int row = linear >> 5;
            int c4  = linear & 31;
            int gr  = row0 + row;
            float4 v = make_float4(0.f, 0.f, 0.f, 0.f);
            if (gr < nRows) {
                v = ((const float4*)(X + (size_t)gr * D))[c4];
                if (mode == 0) {
                    float s = nsrc[gr];
                    v.x *= s; v.y *= s; v.z *= s; v.w *= s;
                } else {
                    float a = ndst[gr];
                    float s = nsrc[gr];
                    float4 bb = ((const float4*)bias)[c4];
                    v.x = fmaxf(fmaf(v.x, a, bb.x), 0.f) * s;
                    v.y = fmaxf(fmaf(v.y, a, bb.y), 0.f) * s;
                    v.z = fmaxf(fmaf(v.z, a, bb.z), 0.f) * s;
                    v.w = fmaxf(fmaf(v.w, a, bb.w), 0.f) * s;
                }
            }
            *(float4*)&Xs[row * 132 + c4 * 4] = v;
        }
    }
    __syncthreads();

    const int tx = tid & 15;        // col group (8 cols each)
    const int ty = tid >> 4;        // row group (4 rows each)
    const int colBase = tx * 8;
    float acc[4][8];
#pragma unroll
    for (int i = 0; i < 4; i++)
#pragma unroll
        for (int j = 0; j < 8; j++) acc[i][j] = 0.f;

#pragma unroll 4
    for (int k = 0; k < D; k++) {
        float4 b0 = *(const float4*)&Ws[k * D + colBase];
        float4 b1 = *(const float4*)&Ws[k * D + colBase + 4];
        float bb[8] = {b0.x, b0.y, b0.z, b0.w, b1.x, b1.y, b1.z, b1.w};
#pragma unroll
        for (int i = 0; i < 4; i++) {
            float a = Xs[(ty * 4 + i) * 132 + k];
#pragma unroll
            for (int j = 0; j < 8; j++) acc[i][j] = fmaf(a, bb[j], acc[i][j]);
        }
    }

#pragma unroll
    for (int i = 0; i < 4; i++) {
        int gr = row0 + ty * 4 + i;
        if (gr < nRows) {
            float4 o0 = make_float4(acc[i][0], acc[i][1], acc[i][2], acc[i][3]);
            float4 o1 = make_float4(acc[i][4], acc[i][5], acc[i][6], acc[i][7]);
            *(float4*)(Y + (size_t)gr * D + colBase)     = o0;
            *(float4*)(Y + (size_t)gr * D + colBase + 4) = o1;
        }
    }
}

// ---------------------------------------------------------------------------
// SpMM scatter: agg[dst] += t[src], one warp per edge, v4 reduction atomics.
// ---------------------------------------------------------------------------
__global__ __launch_bounds__(256) void spmm_kernel(
    const float* __restrict__ t, const int* __restrict__ src,
    const int* __restrict__ dst, float* __restrict__ agg, int nE)
{
    int e = blockIdx.x * 8 + (threadIdx.x >> 5);
    if (e >= nE) return;
    int lane = threadIdx.x & 31;
    int s = src[e];
    int d = dst[e];
    float4 v = *(const float4*)(t + (size_t)s * D + lane * 4);
    float* p = agg + (size_t)d * D + lane * 4;
    asm volatile("red.global.add.v4.f32 [%0], {%1,%2,%3,%4};"
                 :: "l"(p), "f"(v.x), "f"(v.y), "f"(v.z), "f"(v.w)
                 : "memory");
}

// ---------------------------------------------------------------------------
// final epilogue: h = relu(agg * nd[r] + b)  (writes to d_out h-region)
// ---------------------------------------------------------------------------
__global__ void epilogue_h(const float* __restrict__ agg,
                           const float* __restrict__ nd,
                           const float* __restrict__ bias,
                           float* __restrict__ h, int nNodes) {
    int idx4 = blockIdx.x * blockDim.x + threadIdx.x;  // float4 index
    int total = nNodes * (D / 4);
    if (idx4 >= total) return;
    int r  = idx4 >> 5;
    int c4 = idx4 & 31;
    float a = nd[r];
    float4 v  = ((const float4*)agg)[idx4];
    float4 bb = ((const float4*)bias)[c4];
    v.x = fmaxf(fmaf(v.x, a, bb.x), 0.f);
    v.y = fmaxf(fmaf(v.y, a, bb.y), 0.f);
    v.z = fmaxf(fmaf(v.z, a, bb.z), 0.f);
    v.w = fmaxf(fmaf(v.w, a, bb.w), 0.f);
    ((float4*)h)[idx4] = v;
}

// ---------------------------------------------------------------------------
// per-graph mean pooling (graph_id is sorted -> binary-searched ranges)
// ---------------------------------------------------------------------------
__device__ __forceinline__ int lower_bound_i(const int* a, int n, int v) {
    int lo = 0, hi = n;
    while (lo < hi) {
        int mid = (lo + hi) >> 1;
        if (a[mid] < v) lo = mid + 1; else hi = mid;
    }
    return lo;
}

__global__ void pool_kernel(const float* __restrict__ h,
                            const int* __restrict__ gid,
                            int nNodes, float* __restrict__ hg) {
    int g = blockIdx.x;
    int t = threadIdx.x;   // 128 threads, one feature each
    int lo = lower_bound_i(gid, nNodes, g);
    int hi = lower_bound_i(gid, nNodes, g + 1);
    float s0 = 0.f, s1 = 0.f, s2 = 0.f, s3 = 0.f;
    int r = lo;
    for (; r + 3 < hi; r += 4) {
        s0 += h[(size_t)r * D + t];
        s1 += h[(size_t)(r + 1) * D + t];
        s2 += h[(size_t)(r + 2) * D + t];
        s3 += h[(size_t)(r + 3) * D + t];
    }
    for (; r < hi; r++) s0 += h[(size_t)r * D + t];
    float cnt = (float)(hi - lo);
    hg[g * D + t] = ((s0 + s1) + (s2 + s3)) / fmaxf(cnt, 1.0f);
}

// ---------------------------------------------------------------------------
// readout linear: out[g] = (relu?)(in[g] @ W + b); 64 blocks x 128 threads
// ---------------------------------------------------------------------------
__global__ void readout_kernel(const float* __restrict__ in,
                               const float* __restrict__ W,
                               const float* __restrict__ b,
                               float* __restrict__ out, int doRelu) {
    __shared__ float row[D];
    int g = blockIdx.x, t = threadIdx.x;
    row[t] = in[g * D + t];
    __syncthreads();
    float acc = b[t];
#pragma unroll 8
    for (int k = 0; k < D; k++) acc = fmaf(row[k], W[k * D + t], acc);
    if (doRelu) acc = fmaxf(acc, 0.f);
    out[g * D + t] = acc;
}

// ---------------------------------------------------------------------------
extern "C" void kernel_launch(void* const* d_in, const int* in_sizes, int n_in,
                              void* d_out, int out_size) {
    const float* x   = (const float*)d_in[0];
    const int*   ei  = (const int*)d_in[1];
    const int*   gid = (const int*)d_in[2];
    int wbase = (n_in >= 12) ? 4 : 3;   // skip num_graphs scalar if present
    const float* W1  = (const float*)d_in[wbase + 0];
    const float* b1  = (const float*)d_in[wbase + 1];
    const float* W2  = (const float*)d_in[wbase + 2];
    const float* b2  = (const float*)d_in[wbase + 3];
    const float* Wr1 = (const float*)d_in[wbase + 4];
    const float* br1 = (const float*)d_in[wbase + 5];
    const float* Wr2 = (const float*)d_in[wbase + 6];
    const float* br2 = (const float*)d_in[wbase + 7];

    const int nNodes = in_sizes[0] / D;
    const int nE     = in_sizes[1] / 2;
    const int* src = ei;
    const int* dst = ei + nE;

    float* out_g = (float*)d_out;            // (64,128)
    float* out_h = out_g + 64 * D;           // (nNodes,128)

    float *deg, *nrm, *t, *agg, *hg, *tmp;
    cudaGetSymbolAddress((void**)&deg, g_deg);
    cudaGetSymbolAddress((void**)&nrm, g_norm);
    cudaGetSymbolAddress((void**)&t,   g_t);
    cudaGetSymbolAddress((void**)&agg, g_agg);
    cudaGetSymbolAddress((void**)&hg,  g_hg);
    cudaGetSymbolAddress((void**)&tmp, g_tmp);

    float* deg_out = deg;
    float* deg_in  = deg + MAX_NODES;
    float* ns      = nrm;
    float* nd      = nrm + MAX_NODES;
    float* agg1    = agg;
    float* agg2    = agg + (size_t)MAX_FEAT;

    const size_t smemGemm = (size_t)(D * D + 64 * 132) * sizeof(float);
    cudaFuncSetAttribute(gemm_fused, cudaFuncAttributeMaxDynamicSharedMemorySize,
                         (int)smemGemm);

    // zero scratch
    cudaMemsetAsync(deg, 0, 2 * (size_t)MAX_NODES * sizeof(float), 0);
    cudaMemsetAsync(agg, 0, 2 * (size_t)MAX_FEAT * sizeof(float), 0);

    // degrees + norms
    deg_kernel<<<(nE + 255) / 256, 256>>>(src, dst, deg_out, deg_in, nE);
    norm_kernel<<<(nNodes + 255) / 256, 256>>>(deg_out, deg_in, ns, nd, nNodes);

    int gemmBlocks = (nNodes + 63) / 64;
    int spmmBlocks = (nE + 7) / 8;

    // layer 1: t = (x .* ns) @ W1 ; agg1[dst] += t[src]
    gemm_fused<<<gemmBlocks, 256, smemGemm>>>(x, W1, nullptr, ns, nullptr, t,
                                              nNodes, 0);
    spmm_kernel<<<spmmBlocks, 256>>>(t, src, dst, agg1, nE);

    // layer 2: t = (relu(agg1 .* nd + b1) .* ns) @ W2 ; agg2[dst] += t[src]
    gemm_fused<<<gemmBlocks, 256, smemGemm>>>(agg1, W2, b1, ns, nd, t,
                                              nNodes, 1);
    spmm_kernel<<<spmmBlocks, 256>>>(t, src, dst, agg2, nE);

    // final epilogue -> h (in d_out)
    int ep4 = nNodes * (D / 4);
    epilogue_h<<<(ep4 + 255) / 256, 256>>>(agg2, nd, b2, out_h, nNodes);

    // pooling + readout MLP
    pool_kernel<<<64, D>>>(out_h, gid, nNodes, hg);
    readout_kernel<<<64, D>>>(hg, Wr1, br1, tmp, 1);
    readout_kernel<<<64, D>>>(tmp, Wr2, br2, out_g, 0);
}

// round 3
// speedup vs baseline: 1.3631x; 1.3631x over previous
#include <cuda_runtime.h>
#include <cuda_bf16.h>

// ---------------------------------------------------------------------------
// GCN (CSR gather-reduce version):
//   h1 = relu(Dd^-1/2 A (Ds^-1/2 x) W1 + b1)
//   h2 = relu(Dd^-1/2 A (Ds^-1/2 h1) W2 + b2)
//   hg = mean-pool(h2, graph_id); out = relu(hg Wr1 + br1) Wr2 + br2
// Outputs: out (64x128) then h2 (nNodes x 128). Indices are int32.
// ---------------------------------------------------------------------------

#define D 128
#define MAX_NODES 100096
#define MAX_EDGES 1700000
#define MAX_FEAT  12812288   // MAX_NODES * 128

// scratch (device globals: allocation-free rule)
__device__ int   g_hist[2 * MAX_NODES];       // hist_dst, hist_src
__device__ int   g_rowptr[MAX_NODES + 1];
__device__ int   g_cursor[MAX_NODES];
__device__ int   g_esrc[MAX_EDGES];
__device__ int   g_bsums[256];
__device__ int   g_boffs[256];
__device__ float g_norm[2 * MAX_NODES];       // norm_src, norm_dst
__device__ float g_t[MAX_FEAT];               // GEMM output (both layers)
__device__ float g_agg[MAX_FEAT];             // layer-1 aggregate
__device__ float g_hg[64 * D];
__device__ float g_tmp[64 * D];

// ---------------------------------------------------------------------------
__global__ void hist_kernel(const int* __restrict__ src,
                            const int* __restrict__ dst,
                            int* __restrict__ hdst, int* __restrict__ hsrc,
                            int nE) {
    int e = blockIdx.x * blockDim.x + threadIdx.x;
    if (e < nE) {
        atomicAdd(&hdst[dst[e]], 1);
        atomicAdd(&hsrc[src[e]], 1);
    }
}

__global__ void norm_kernel(const int* __restrict__ hsrc,
                            const int* __restrict__ hdst,
                            float* __restrict__ ns, float* __restrict__ nd,
                            int n) {
    int i = blockIdx.x * blockDim.x + threadIdx.x;
    if (i < n) {
        ns[i] = rsqrtf(fmaxf((float)hsrc[i], 1.0f));
        nd[i] = rsqrtf(fmaxf((float)hdst[i], 1.0f));
    }
}

// ---------------- 3-kernel exclusive prefix scan over hist_dst -------------
__global__ void scan_bsums(const int* __restrict__ hist,
                           int* __restrict__ bsums, int n) {
    __shared__ int sh[256];
    int b = blockIdx.x, t = threadIdx.x;
    int base = b * 1024 + t * 4;
    int s = 0;
#pragma unroll
    for (int k = 0; k < 4; k++) { int i = base + k; if (i < n) s += hist[i]; }
    sh[t] = s; __syncthreads();
    for (int off = 128; off > 0; off >>= 1) {
        if (t < off) sh[t] += sh[t + off];
        __syncthreads();
    }
    if (t == 0) bsums[b] = sh[0];
}

__global__ void scan_offsets(const int* __restrict__ bsums,
                             int* __restrict__ boffs, int nb) {
    __shared__ int sh[256];
    int t = threadIdx.x;
    int v0 = (t < nb) ? bsums[t] : 0;
    sh[t] = v0; __syncthreads();
    for (int off = 1; off < 256; off <<= 1) {
        int u = (t >= off) ? sh[t - off] : 0;
        __syncthreads();
        sh[t] += u;
        __syncthreads();
    }
    boffs[t] = sh[t] - v0;   // exclusive
}

__global__ void scan_expand(const int* __restrict__ hist,
                            const int* __restrict__ boffs,
                            int* __restrict__ rowptr, int* __restrict__ cursor,
                            int n, int nE) {
    __shared__ int sh[256];
    int b = blockIdx.x, t = threadIdx.x;
    int base = b * 1024 + t * 4;
    int v[4]; int s = 0;
#pragma unroll
    for (int k = 0; k < 4; k++) {
        int i = base + k;
        v[k] = (i < n) ? hist[i] : 0;
        s += v[k];
    }
    sh[t] = s; __syncthreads();
    for (int off = 1; off < 256; off <<= 1) {
        int u = (t >= off) ? sh[t - off] : 0;
        __syncthreads();
        sh[t] += u;
        __syncthreads();
    }
    int off = boffs[b] + sh[t] - s;   // exclusive offset for this thread's 4
#pragma unroll
    for (int k = 0; k < 4; k++) {
        int i = base + k;
        if (i < n) { rowptr[i] = off; cursor[i] = off; }
        off += v[k];
    }
    if (b == 0 && t == 0) rowptr[n] = nE;
}

__global__ void scatter_edges(const int* __restrict__ src,
                              const int* __restrict__ dst,
                              int* __restrict__ cursor,
                              int* __restrict__ esrc, int nE) {
    int e = blockIdx.x * blockDim.x + threadIdx.x;
    if (e < nE) {
        int p = atomicAdd(&cursor[dst[e]], 1);
        esrc[p] = src[e];
    }
}

// ---------------------------------------------------------------------------
// Fused GEMM: Y[r] = f(X[r]) @ W, K = N = 128.
// mode 0: f(x)[k] = x[k] * nsrc[r]
// mode 1: f(x)[k] = relu(x[k]*ndst[r] + bias[k]) * nsrc[r]
// ---------------------------------------------------------------------------
__global__ __launch_bounds__(256, 1) void gemm_fused(
    const float* __restrict__ X, const float* __restrict__ W,
    const float* __restrict__ bias, const float* __restrict__ nsrc,
    const float* __restrict__ ndst, float* __restrict__ Y,
    int nRows, int mode)
{
    extern __shared__ float sm[];
    float* Ws = sm;                 // 128*128
    float* Xs = sm + D * D;         // 64*132
    const int tid = threadIdx.x;
    const int row0 = blockIdx.x * 64;

    {
        const float4* Wg = (const float4*)W;
        float4* Wsm = (float4*)Ws;
#pragma unroll
        for (int i = 0; i < 16; i++) Wsm[tid + i * 256] = Wg[tid + i * 256];
    }
    {
#pragma unroll
        for (int i = 0; i < 8; i++) {
            int linear = tid + i * 256;
            int row = linear >> 5;
            int c4  = linear & 31;
            int gr  = row0 + row;
            float4 v = make_float4(0.f, 0.f, 0.f, 0.f);
            if (gr < nRows) {
                v = ((const float4*)(X + (size_t)gr * D))[c4];
                if (mode == 0) {
                    float s = nsrc[gr];
                    v.x *= s; v.y *= s; v.z *= s; v.w *= s;
                } else {
                    float a = ndst[gr];
                    float s = nsrc[gr];
                    float4 bb = ((const float4*)bias)[c4];
                    v.x = fmaxf(fmaf(v.x, a, bb.x), 0.f) * s;
                    v.y = fmaxf(fmaf(v.y, a, bb.y), 0.f) * s;
                    v.z = fmaxf(fmaf(v.z, a, bb.z), 0.f) * s;
                    v.w = fmaxf(fmaf(v.w, a, bb.w), 0.f) * s;
                }
            }
            *(float4*)&Xs[row * 132 + c4 * 4] = v;
        }
    }
    __syncthreads();

    const int tx = tid & 15;
    const int ty = tid >> 4;
    const int colBase = tx * 8;
    float acc[4][8];
#pragma unroll
    for (int i = 0; i < 4; i++)
#pragma unroll
        for (int j = 0; j < 8; j++) acc[i][j] = 0.f;

#pragma unroll 4
    for (int k = 0; k < D; k++) {
        float4 b0 = *(const float4*)&Ws[k * D + colBase];
        float4 b1 = *(const float4*)&Ws[k * D + colBase + 4];
        float bb[8] = {b0.x, b0.y, b0.z, b0.w, b1.x, b1.y, b1.z, b1.w};
#pragma unroll
        for (int i = 0; i < 4; i++) {
            float a = Xs[(ty * 4 + i) * 132 + k];
#pragma unroll
            for (int j = 0; j < 8; j++) acc[i][j] = fmaf(a, bb[j], acc[i][j]);
        }
    }

#pragma unroll
    for (int i = 0; i < 4; i++) {
        int gr = row0 + ty * 4 + i;
        if (gr < nRows) {
            *(float4*)(Y + (size_t)gr * D + colBase) =
                make_float4(acc[i][0], acc[i][1], acc[i][2], acc[i][3]);
            *(float4*)(Y + (size_t)gr * D + colBase + 4) =
                make_float4(acc[i][4], acc[i][5], acc[i][6], acc[i][7]);
        }
    }
}

// ---------------------------------------------------------------------------
// CSR SpMM gather-reduce: one warp per dst node, float4 per lane.
// MODE 0: out[node] = sum_{e in row} t[src[e]]                  (raw agg)
// MODE 1: out[node] = relu(sum * nd[node] + bias)               (final h)
// ---------------------------------------------------------------------------
template<int MODE>
__global__ __launch_bounds__(256) void csr_spmm(
    const float* __restrict__ t, const int* __restrict__ rowptr,
    const int* __restrict__ esrc, const float* __restrict__ nd,
    const float* __restrict__ bias, float* __restrict__ out, int nNodes)
{
    int node = blockIdx.x * 8 + (threadIdx.x >> 5);
    if (node >= nNodes) return;
    int lane = threadIdx.x & 31;
    int beg = rowptr[node];
    int end = rowptr[node + 1];

    float4 a0 = make_float4(0.f, 0.f, 0.f, 0.f);
    float4 a1 = make_float4(0.f, 0.f, 0.f, 0.f);
    float4 a2 = make_float4(0.f, 0.f, 0.f, 0.f);
    float4 a3 = make_float4(0.f, 0.f, 0.f, 0.f);

    int j = beg;
    for (; j + 3 < end; j += 4) {
        int s0 = esrc[j], s1 = esrc[j + 1], s2 = esrc[j + 2], s3 = esrc[j + 3];
        float4 v0 = __ldg((const float4*)(t + (size_t)s0 * D) + lane);
        float4 v1 = __ldg((const float4*)(t + (size_t)s1 * D) + lane);
        float4 v2 = __ldg((const float4*)(t + (size_t)s2 * D) + lane);
        float4 v3 = __ldg((const float4*)(t + (size_t)s3 * D) + lane);
        a0.x += v0.x; a0.y += v0.y; a0.z += v0.z; a0.w += v0.w;
        a1.x += v1.x; a1.y += v1.y; a1.z += v1.z; a1.w += v1.w;
        a2.x += v2.x; a2.y += v2.y; a2.z += v2.z; a2.w += v2.w;
        a3.x += v3.x; a3.y += v3.y; a3.z += v3.z; a3.w += v3.w;
    }
    for (; j < end; j++) {
        int s = esrc[j];
        float4 v = __ldg((const float4*)(t + (size_t)s * D) + lane);
        a0.x += v.x; a0.y += v.y; a0.z += v.z; a0.w += v.w;
    }
    float4 acc;
    acc.x = (a0.x + a1.x) + (a2.x + a3.x);
    acc.y = (a0.y + a1.y) + (a2.y + a3.y);
    acc.z = (a0.z + a1.z) + (a2.z + a3.z);
    acc.w = (a0.w + a1.w) + (a2.w + a3.w);

    if (MODE == 1) {
        float a = nd[node];
        float4 bb = __ldg((const float4*)bias + lane);
        acc.x = fmaxf(fmaf(acc.x, a, bb.x), 0.f);
        acc.y = fmaxf(fmaf(acc.y, a, bb.y), 0.f);
        acc.z = fmaxf(fmaf(acc.z, a, bb.z), 0.f);
        acc.w = fmaxf(fmaf(acc.w, a, bb.w), 0.f);
    }
    *(float4*)(out + (size_t)node * D + lane * 4) = acc;
}

// ---------------------------------------------------------------------------
__device__ __forceinline__ int lower_bound_i(const int* a, int n, int v) {
    int lo = 0, hi = n;
    while (lo < hi) {
        int mid = (lo + hi) >> 1;
        if (a[mid] < v) lo = mid + 1; else hi = mid;
    }
    return lo;
}

__global__ void pool_kernel(const float* __restrict__ h,
                            const int* __restrict__ gid,
                            int nNodes, float* __restrict__ hg) {
    int g = blockIdx.x;
    int t = threadIdx.x;
    int lo = lower_bound_i(gid, nNodes, g);
    int hi = lower_bound_i(gid, nNodes, g + 1);
    float s0 = 0.f, s1 = 0.f, s2 = 0.f, s3 = 0.f;
    int r = lo;
    for (; r + 3 < hi; r += 4) {
        s0 += h[(size_t)r * D + t];
        s1 += h[(size_t)(r + 1) * D + t];
        s2 += h[(size_t)(r + 2) * D + t];
        s3 += h[(size_t)(r + 3) * D + t];
    }
    for (; r < hi; r++) s0 += h[(size_t)r * D + t];
    float cnt = (float)(hi - lo);
    hg[g * D + t] = ((s0 + s1) + (s2 + s3)) / fmaxf(cnt, 1.0f);
}

__global__ void readout_kernel(const float* __restrict__ in,
                               const float* __restrict__ W,
                               const float* __restrict__ b,
                               float* __restrict__ out, int doRelu) {
    __shared__ float row[D];
    int g = blockIdx.x, t = threadIdx.x;
    row[t] = in[g * D + t];
    __syncthreads();
    float acc = b[t];
#pragma unroll 8
    for (int k = 0; k < D; k++) acc = fmaf(row[k], W[k * D + t], acc);
    if (doRelu) acc = fmaxf(acc, 0.f);
    out[g * D + t] = acc;
}

// ---------------------------------------------------------------------------
extern "C" void kernel_launch(void* const* d_in, const int* in_sizes, int n_in,
                              void* d_out, int out_size) {
    const float* x   = (const float*)d_in[0];
    const int*   ei  = (const int*)d_in[1];
    const int*   gid = (const int*)d_in[2];
    int wbase = (n_in >= 12) ? 4 : 3;
    const float* W1  = (const float*)d_in[wbase + 0];
    const float* b1  = (const float*)d_in[wbase + 1];
    const float* W2  = (const float*)d_in[wbase + 2];
    const float* b2  = (const float*)d_in[wbase + 3];
    const float* Wr1 = (const float*)d_in[wbase + 4];
    const float* br1 = (const float*)d_in[wbase + 5];
    const float* Wr2 = (const float*)d_in[wbase + 6];
    const float* br2 = (const float*)d_in[wbase + 7];

    const int nNodes = in_sizes[0] / D;
    const int nE     = in_sizes[1] / 2;
    const int* src = ei;
    const int* dst = ei + nE;

    float* out_g = (float*)d_out;
    float* out_h = out_g + 64 * D;

    int   *hist, *rowptr, *cursor, *esrc, *bsums, *boffs;
    float *nrm, *t, *agg, *hg, *tmp;
    cudaGetSymbolAddress((void**)&hist,   g_hist);
    cudaGetSymbolAddress((void**)&rowptr, g_rowptr);
    cudaGetSymbolAddress((void**)&cursor, g_cursor);
    cudaGetSymbolAddress((void**)&esrc,   g_esrc);
    cudaGetSymbolAddress((void**)&bsums,  g_bsums);
    cudaGetSymbolAddress((void**)&boffs,  g_boffs);
    cudaGetSymbolAddress((void**)&nrm,    g_norm);
    cudaGetSymbolAddress((void**)&t,      g_t);
    cudaGetSymbolAddress((void**)&agg,    g_agg);
    cudaGetSymbolAddress((void**)&hg,     g_hg);
    cudaGetSymbolAddress((void**)&tmp,    g_tmp);

    int* hdst = hist;
    int* hsrc = hist + MAX_NODES;
    float* ns = nrm;
    float* nd = nrm + MAX_NODES;

    const size_t smemGemm = (size_t)(D * D + 64 * 132) * sizeof(float);
    cudaFuncSetAttribute(gemm_fused, cudaFuncAttributeMaxDynamicSharedMemorySize,
                         (int)smemGemm);

    const int nb = (nNodes + 1023) / 1024;

    // CSR build + norms
    cudaMemsetAsync(hist, 0, 2 * (size_t)MAX_NODES * sizeof(int), 0);
    hist_kernel<<<(nE + 255) / 256, 256>>>(src, dst, hdst, hsrc, nE);
    norm_kernel<<<(nNodes + 255) / 256, 256>>>(hsrc, hdst, ns, nd, nNodes);
    scan_bsums<<<nb, 256>>>(hdst, bsums, nNodes);
    scan_offsets<<<1, 256>>>(bsums, boffs, nb);
    scan_expand<<<nb, 256>>>(hdst, boffs, rowptr, cursor, nNodes, nE);
    scatter_edges<<<(nE + 255) / 256, 256>>>(src, dst, cursor, esrc, nE);

    int gemmBlocks = (nNodes + 63) / 64;
    int spmmBlocks = (nNodes + 7) / 8;

    // layer 1
    gemm_fused<<<gemmBlocks, 256, smemGemm>>>(x, W1, nullptr, ns, nullptr, t,
                                              nNodes, 0);
    csr_spmm<0><<<spmmBlocks, 256>>>(t, rowptr, esrc, nullptr, nullptr, agg,
                                     nNodes);

    // layer 2 (epilogue fused: writes h directly into d_out)
    gemm_fused<<<gemmBlocks, 256, smemGemm>>>(agg, W2, b1, ns, nd, t,
                                              nNodes, 1);
    csr_spmm<1><<<spmmBlocks, 256>>>(t, rowptr, esrc, nd, b2, out_h, nNodes);

    // pooling + readout MLP
    pool_kernel<<<64, D>>>(out_h, gid, nNodes, hg);
    readout_kernel<<<64, D>>>(hg, Wr1, br1, tmp, 1);
    readout_kernel<<<64, D>>>(tmp, Wr2, br2, out_g, 0);
}

// round 4
// speedup vs baseline: 1.5391x; 1.1292x over previous
#include <cuda_runtime.h>
#include <cuda_fp16.h>

// ---------------------------------------------------------------------------
// GCN (CSR gather-reduce, fp16 intermediate):
//   h1 = relu(Dd^-1/2 A (Ds^-1/2 x) W1 + b1)
//   h2 = relu(Dd^-1/2 A (Ds^-1/2 h1) W2 + b2)
//   hg = mean-pool(h2, graph_id); out = relu(hg Wr1 + br1) Wr2 + br2
// Outputs: out (64x128) then h2 (nNodes x 128). Indices are int32.
// t (GEMM output / SpMM gather input) stored fp16 to halve L2 traffic.
// ---------------------------------------------------------------------------

#define D 128
#define MAX_NODES 100096
#define MAX_EDGES 1700000
#define MAX_FEAT  12812288   // MAX_NODES * 128

// scratch (device globals: allocation-free rule)
__device__ int    g_hist[2 * MAX_NODES];       // hist_dst, hist_src
__device__ int    g_rowptr[MAX_NODES + 1];
__device__ int    g_cursor[MAX_NODES];
__device__ int    g_esrc[MAX_EDGES];
__device__ int    g_bsums[256];
__device__ int    g_boffs[256];
__device__ float  g_norm[2 * MAX_NODES];       // norm_src, norm_dst
__device__ __half g_t[MAX_FEAT];               // GEMM output (fp16, both layers)
__device__ float  g_agg[MAX_FEAT];             // layer-1 aggregate (fp32)
__device__ float  g_hg[64 * D];
__device__ float  g_tmp[64 * D];

// ---------------------------------------------------------------------------
__global__ void hist_kernel(const int* __restrict__ src,
                            const int* __restrict__ dst,
                            int* __restrict__ hdst, int* __restrict__ hsrc,
                            int nE) {
    int e = blockIdx.x * blockDim.x + threadIdx.x;
    if (e < nE) {
        atomicAdd(&hdst[dst[e]], 1);
        atomicAdd(&hsrc[src[e]], 1);
    }
}

__global__ void norm_kernel(const int* __restrict__ hsrc,
                            const int* __restrict__ hdst,
                            float* __restrict__ ns, float* __restrict__ nd,
                            int n) {
    int i = blockIdx.x * blockDim.x + threadIdx.x;
    if (i < n) {
        ns[i] = rsqrtf(fmaxf((float)hsrc[i], 1.0f));
        nd[i] = rsqrtf(fmaxf((float)hdst[i], 1.0f));
    }
}

// ---------------- 3-kernel exclusive prefix scan over hist_dst -------------
__global__ void scan_bsums(const int* __restrict__ hist,
                           int* __restrict__ bsums, int n) {
    __shared__ int sh[256];
    int b = blockIdx.x, t = threadIdx.x;
    int base = b * 1024 + t * 4;
    int s = 0;
#pragma unroll
    for (int k = 0; k < 4; k++) { int i = base + k; if (i < n) s += hist[i]; }
    sh[t] = s; __syncthreads();
    for (int off = 128; off > 0; off >>= 1) {
        if (t < off) sh[t] += sh[t + off];
        __syncthreads();
    }
    if (t == 0) bsums[b] = sh[0];
}

__global__ void scan_offsets(const int* __restrict__ bsums,
                             int* __restrict__ boffs, int nb) {
    __shared__ int sh[256];
    int t = threadIdx.x;
    int v0 = (t < nb) ? bsums[t] : 0;
    sh[t] = v0; __syncthreads();
    for (int off = 1; off < 256; off <<= 1) {
        int u = (t >= off) ? sh[t - off] : 0;
        __syncthreads();
        sh[t] += u;
        __syncthreads();
    }
    boffs[t] = sh[t] - v0;   // exclusive
}

__global__ void scan_expand(const int* __restrict__ hist,
                            const int* __restrict__ boffs,
                            int* __restrict__ rowptr, int* __restrict__ cursor,
                            int n, int nE) {
    __shared__ int sh[256];
    int b = blockIdx.x, t = threadIdx.x;
    int base = b * 1024 + t * 4;
    int v[4]; int s = 0;
#pragma unroll
    for (int k = 0; k < 4; k++) {
        int i = base + k;
        v[k] = (i < n) ? hist[i] : 0;
        s += v[k];
    }
    sh[t] = s; __syncthreads();
    for (int off = 1; off < 256; off <<= 1) {
        int u = (t >= off) ? sh[t - off] : 0;
        __syncthreads();
        sh[t] += u;
        __syncthreads();
    }
    int off = boffs[b] + sh[t] - s;
#pragma unroll
    for (int k = 0; k < 4; k++) {
        int i = base + k;
        if (i < n) { rowptr[i] = off; cursor[i] = off; }
        off += v[k];
    }
    if (b == 0 && t == 0) rowptr[n] = nE;
}

__global__ void scatter_edges(const int* __restrict__ src,
                              const int* __restrict__ dst,
                              int* __restrict__ cursor,
                              int* __restrict__ esrc, int nE) {
    int e = blockIdx.x * blockDim.x + threadIdx.x;
    if (e < nE) {
        int p = atomicAdd(&cursor[dst[e]], 1);
        esrc[p] = src[e];
    }
}

// ---------------------------------------------------------------------------
// Fused GEMM: Y[r] = f(X[r]) @ W, K = N = 128, Y stored fp16.
// mode 0: f(x)[k] = x[k] * nsrc[r]
// mode 1: f(x)[k] = relu(x[k]*ndst[r] + bias[k]) * nsrc[r]
// ---------------------------------------------------------------------------
__global__ __launch_bounds__(256, 1) void gemm_fused(
    const float* __restrict__ X, const float* __restrict__ W,
    const float* __restrict__ bias, const float* __restrict__ nsrc,
    const float* __restrict__ ndst, __half* __restrict__ Y,
    int nRows, int mode)
{
    extern __shared__ float sm[];
    float* Ws = sm;                 // 128*128
    float* Xs = sm + D * D;         // 64*132
    const int tid = threadIdx.x;
    const int row0 = blockIdx.x * 64;

    {
        const float4* Wg = (const float4*)W;
        float4* Wsm = (float4*)Ws;
#pragma unroll
        for (int i = 0; i < 16; i++) Wsm[tid + i * 256] = Wg[tid + i * 256];
    }
    {
#pragma unroll
        for (int i = 0; i < 8; i++) {
            int linear = tid + i * 256;
            int row = linear >> 5;
            int c4  = linear & 31;
            int gr  = row0 + row;
            float4 v = make_float4(0.f, 0.f, 0.f, 0.f);
            if (gr < nRows) {
                v = ((const float4*)(X + (size_t)gr * D))[c4];
                if (mode == 0) {
                    float s = nsrc[gr];
                    v.x *= s; v.y *= s; v.z *= s; v.w *= s;
                } else {
                    float a = ndst[gr];
                    float s = nsrc[gr];
                    float4 bb = ((const float4*)bias)[c4];
                    v.x = fmaxf(fmaf(v.x, a, bb.x), 0.f) * s;
                    v.y = fmaxf(fmaf(v.y, a, bb.y), 0.f) * s;
                    v.z = fmaxf(fmaf(v.z, a, bb.z), 0.f) * s;
                    v.w = fmaxf(fmaf(v.w, a, bb.w), 0.f) * s;
                }
            }
            *(float4*)&Xs[row * 132 + c4 * 4] = v;
        }
    }
    __syncthreads();

    const int tx = tid & 15;
    const int ty = tid >> 4;
    const int colBase = tx * 8;
    float acc[4][8];
#pragma unroll
    for (int i = 0; i < 4; i++)
#pragma unroll
        for (int j = 0; j < 8; j++) acc[i][j] = 0.f;

#pragma unroll 4
    for (int k = 0; k < D; k++) {
        float4 b0 = *(const float4*)&Ws[k * D + colBase];
        float4 b1 = *(const float4*)&Ws[k * D + colBase + 4];
        float bb[8] = {b0.x, b0.y, b0.z, b0.w, b1.x, b1.y, b1.z, b1.w};
#pragma unroll
        for (int i = 0; i < 4; i++) {
            float a = Xs[(ty * 4 + i) * 132 + k];
#pragma unroll
            for (int j = 0; j < 8; j++) acc[i][j] = fmaf(a, bb[j], acc[i][j]);
        }
    }

#pragma unroll
    for (int i = 0; i < 4; i++) {
        int gr = row0 + ty * 4 + i;
        if (gr < nRows) {
            __half2 h0 = __floats2half2_rn(acc[i][0], acc[i][1]);
            __half2 h1 = __floats2half2_rn(acc[i][2], acc[i][3]);
            __half2 h2 = __floats2half2_rn(acc[i][4], acc[i][5]);
            __half2 h3 = __floats2half2_rn(acc[i][6], acc[i][7]);
            uint4 pack;
            pack.x = *(unsigned*)&h0; pack.y = *(unsigned*)&h1;
            pack.z = *(unsigned*)&h2; pack.w = *(unsigned*)&h3;
            *(uint4*)(Y + (size_t)gr * D + colBase) = pack;
        }
    }
}

// ---------------------------------------------------------------------------
// CSR SpMM gather-reduce (fp16 t): one warp per dst node.
// Lane covers 4 features: loads uint2 (4 halfs) per edge, fp32 accumulate.
// MODE 0: out[node] = sum_{e in row} t[src[e]]            (fp32 raw agg)
// MODE 1: out[node] = relu(sum * nd[node] + bias)         (final h, fp32)
// ---------------------------------------------------------------------------
template<int MODE>
__global__ __launch_bounds__(256) void csr_spmm(
    const __half* __restrict__ t, const int* __restrict__ rowptr,
    const int* __restrict__ esrc, const float* __restrict__ nd,
    const float* __restrict__ bias, float* __restrict__ out, int nNodes)
{
    int node = blockIdx.x * 8 + (threadIdx.x >> 5);
    if (node >= nNodes) return;
    int lane = threadIdx.x & 31;
    int beg = rowptr[node];
    int end = rowptr[node + 1];

    float4 a0 = make_float4(0.f, 0.f, 0.f, 0.f);
    float4 a1 = make_float4(0.f, 0.f, 0.f, 0.f);
    float4 a2 = make_float4(0.f, 0.f, 0.f, 0.f);
    float4 a3 = make_float4(0.f, 0.f, 0.f, 0.f);

#define ACCUM(ACC, U)                                                     \
    {                                                                     \
        float2 f0 = __half22float2(*(const __half2*)&(U).x);              \
        float2 f1 = __half22float2(*(const __half2*)&(U).y);              \
        (ACC).x += f0.x; (ACC).y += f0.y; (ACC).z += f1.x; (ACC).w += f1.y;\
    }

    int j = beg;
    for (; j + 3 < end; j += 4) {
        int s0 = esrc[j], s1 = esrc[j + 1], s2 = esrc[j + 2], s3 = esrc[j + 3];
        uint2 v0 = __ldg((const uint2*)(t + (size_t)s0 * D) + lane);
        uint2 v1 = __ldg((const uint2*)(t + (size_t)s1 * D) + lane);
        uint2 v2 = __ldg((const uint2*)(t + (size_t)s2 * D) + lane);
        uint2 v3 = __ldg((const uint2*)(t + (size_t)s3 * D) + lane);
        ACCUM(a0, v0); ACCUM(a1, v1); ACCUM(a2, v2); ACCUM(a3, v3);
    }
    for (; j < end; j++) {
        int s = esrc[j];
        uint2 v = __ldg((const uint2*)(t + (size_t)s * D) + lane);
        ACCUM(a0, v);
    }
#undef ACCUM

    float4 acc;
    acc.x = (a0.x + a1.x) + (a2.x + a3.x);
    acc.y = (a0.y + a1.y) + (a2.y + a3.y);
    acc.z = (a0.z + a1.z) + (a2.z + a3.z);
    acc.w = (a0.w + a1.w) + (a2.w + a3.w);

    if (MODE == 1) {
        float a = nd[node];
        float4 bb = __ldg((const float4*)bias + lane);
        acc.x = fmaxf(fmaf(acc.x, a, bb.x), 0.f);
        acc.y = fmaxf(fmaf(acc.y, a, bb.y), 0.f);
        acc.z = fmaxf(fmaf(acc.z, a, bb.z), 0.f);
        acc.w = fmaxf(fmaf(acc.w, a, bb.w), 0.f);
    }
    *(float4*)(out + (size_t)node * D + lane * 4) = acc;
}

// ---------------------------------------------------------------------------
__device__ __forceinline__ int lower_bound_i(const int* a, int n, int v) {
    int lo = 0, hi = n;
    while (lo < hi) {
        int mid = (lo + hi) >> 1;
        if (a[mid] < v) lo = mid + 1; else hi = mid;
    }
    return lo;
}

__global__ void pool_kernel(const float* __restrict__ h,
                            const int* __restrict__ gid,
                            int nNodes, float* __restrict__ hg) {
    int g = blockIdx.x;
    int t = threadIdx.x;
    int lo = lower_bound_i(gid, nNodes, g);
    int hi = lower_bound_i(gid, nNodes, g + 1);
    float s0 = 0.f, s1 = 0.f, s2 = 0.f, s3 = 0.f;
    int r = lo;
    for (; r + 3 < hi; r += 4) {
        s0 += h[(size_t)r * D + t];
        s1 += h[(size_t)(r + 1) * D + t];
        s2 += h[(size_t)(r + 2) * D + t];
        s3 += h[(size_t)(r + 3) * D + t];
    }
    for (; r < hi; r++) s0 += h[(size_t)r * D + t];
    float cnt = (float)(hi - lo);
    hg[g * D + t] = ((s0 + s1) + (s2 + s3)) / fmaxf(cnt, 1.0f);
}

__global__ void readout_kernel(const float* __restrict__ in,
                               const float* __restrict__ W,
                               const float* __restrict__ b,
                               float* __restrict__ out, int doRelu) {
    __shared__ float row[D];
    int g = blockIdx.x, t = threadIdx.x;
    row[t] = in[g * D + t];
    __syncthreads();
    float acc = b[t];
#pragma unroll 8
    for (int k = 0; k < D; k++) acc = fmaf(row[k], W[k * D + t], acc);
    if (doRelu) acc = fmaxf(acc, 0.f);
    out[g * D + t] = acc;
}

// ---------------------------------------------------------------------------
extern "C" void kernel_launch(void* const* d_in, const int* in_sizes, int n_in,
                              void* d_out, int out_size) {
    const float* x   = (const float*)d_in[0];
    const int*   ei  = (const int*)d_in[1];
    const int*   gid = (const int*)d_in[2];
    int wbase = (n_in >= 12) ? 4 : 3;
    const float* W1  = (const float*)d_in[wbase + 0];
    const float* b1  = (const float*)d_in[wbase + 1];
    const float* W2  = (const float*)d_in[wbase + 2];
    const float* b2  = (const float*)d_in[wbase + 3];
    const float* Wr1 = (const float*)d_in[wbase + 4];
    const float* br1 = (const float*)d_in[wbase + 5];
    const float* Wr2 = (const float*)d_in[wbase + 6];
    const float* br2 = (const float*)d_in[wbase + 7];

    const int nNodes = in_sizes[0] / D;
    const int nE     = in_sizes[1] / 2;
    const int* src = ei;
    const int* dst = ei + nE;

    float* out_g = (float*)d_out;
    float* out_h = out_g + 64 * D;

    int    *hist, *rowptr, *cursor, *esrc, *bsums, *boffs;
    float  *nrm, *agg, *hg, *tmp;
    __half *t;
    cudaGetSymbolAddress((void**)&hist,   g_hist);
    cudaGetSymbolAddress((void**)&rowptr, g_rowptr);
    cudaGetSymbolAddress((void**)&cursor, g_cursor);
    cudaGetSymbolAddress((void**)&esrc,   g_esrc);
    cudaGetSymbolAddress((void**)&bsums,  g_bsums);
    cudaGetSymbolAddress((void**)&boffs,  g_boffs);
    cudaGetSymbolAddress((void**)&nrm,    g_norm);
    cudaGetSymbolAddress((void**)&t,      g_t);
    cudaGetSymbolAddress((void**)&agg,    g_agg);
    cudaGetSymbolAddress((void**)&hg,     g_hg);
    cudaGetSymbolAddress((void**)&tmp,    g_tmp);

    int* hdst = hist;
    int* hsrc = hist + MAX_NODES;
    float* ns = nrm;
    float* nd = nrm + MAX_NODES;

    const size_t smemGemm = (size_t)(D * D + 64 * 132) * sizeof(float);
    cudaFuncSetAttribute(gemm_fused, cudaFuncAttributeMaxDynamicSharedMemorySize,
                         (int)smemGemm);

    const int nb = (nNodes + 1023) / 1024;

    // CSR build + norms
    cudaMemsetAsync(hist, 0, 2 * (size_t)MAX_NODES * sizeof(int), 0);
    hist_kernel<<<(nE + 255) / 256, 256>>>(src, dst, hdst, hsrc, nE);
    norm_kernel<<<(nNodes + 255) / 256, 256>>>(hsrc, hdst, ns, nd, nNodes);
    scan_bsums<<<nb, 256>>>(hdst, bsums, nNodes);
    scan_offsets<<<1, 256>>>(bsums, boffs, nb);
    scan_expand<<<nb, 256>>>(hdst, boffs, rowptr, cursor, nNodes, nE);
    scatter_edges<<<(nE + 255) / 256, 256>>>(src, dst, cursor, esrc, nE);

    int gemmBlocks = (nNodes + 63) / 64;
    int spmmBlocks = (nNodes + 7) / 8;

    // layer 1
    gemm_fused<<<gemmBlocks, 256, smemGemm>>>(x, W1, nullptr, ns, nullptr, t,
                                              nNodes, 0);
    csr_spmm<0><<<spmmBlocks, 256>>>(t, rowptr, esrc, nullptr, nullptr, agg,
                                     nNodes);

    // layer 2 (epilogue fused: writes h directly into d_out)
    gemm_fused<<<gemmBlocks, 256, smemGemm>>>(agg, W2, b1, ns, nd, t,
                                              nNodes, 1);
    csr_spmm<1><<<spmmBlocks, 256>>>(t, rowptr, esrc, nd, b2, out_h, nNodes);

    // pooling + readout MLP
    pool_kernel<<<64, D>>>(out_h, gid, nNodes, hg);
    readout_kernel<<<64, D>>>(hg, Wr1, br1, tmp, 1);
    readout_kernel<<<64, D>>>(tmp, Wr2, br2, out_g, 0);
}

// round 5
// speedup vs baseline: 2.3419x; 1.5216x over previous
#include <cuda_runtime.h>
#include <cuda_fp16.h>

// ---------------------------------------------------------------------------
// GCN (CSR gather-reduce, fp16 intermediates, HMMA GEMM):
//   h1 = relu(Dd^-1/2 A (Ds^-1/2 x) W1 + b1)
//   h2 = relu(Dd^-1/2 A (Ds^-1/2 h1) W2 + b2)
//   hg = mean-pool(h2, graph_id); out = relu(hg Wr1 + br1) Wr2 + br2
// Outputs: out (64x128) then h2 (nNodes x 128). Indices are int32.
// ---------------------------------------------------------------------------

#define D 128
#define MAX_NODES 100096
#define MAX_EDGES 1700000
#define MAX_FEAT  12812288   // MAX_NODES * 128

// smem strides (halfs) — 136 = 128 + 8 pad => conflict-free ldmatrix
#define WS_STRIDE 136
#define XS_STRIDE 136

// scratch (device globals: allocation-free rule)
__device__ int    g_hist[2 * MAX_NODES];
__device__ int    g_rowptr[MAX_NODES + 1];
__device__ int    g_cursor[MAX_NODES];
__device__ int    g_esrc[MAX_EDGES];
__device__ int    g_bsums[256];
__device__ int    g_boffs[256];
__device__ float  g_norm[2 * MAX_NODES];       // norm_src, norm_dst
__device__ __half g_t[MAX_FEAT];               // GEMM output (fp16)
__device__ float  g_agg[MAX_FEAT];             // layer-1 aggregate (fp32)
__device__ float  g_hg[64 * D];
__device__ float  g_tmp[64 * D];

// ---------------------------------------------------------------------------
__global__ void hist_kernel(const int* __restrict__ src,
                            const int* __restrict__ dst,
                            int* __restrict__ hdst, int* __restrict__ hsrc,
                            int nE) {
    int e = blockIdx.x * blockDim.x + threadIdx.x;
    if (e < nE) {
        atomicAdd(&hdst[dst[e]], 1);
        atomicAdd(&hsrc[src[e]], 1);
    }
}

__global__ void norm_kernel(const int* __restrict__ hsrc,
                            const int* __restrict__ hdst,
                            float* __restrict__ ns, float* __restrict__ nd,
                            int n) {
    int i = blockIdx.x * blockDim.x + threadIdx.x;
    if (i < n) {
        ns[i] = rsqrtf(fmaxf((float)hsrc[i], 1.0f));
        nd[i] = rsqrtf(fmaxf((float)hdst[i], 1.0f));
    }
}

// ---------------- 3-kernel exclusive prefix scan over hist_dst -------------
__global__ void scan_bsums(const int* __restrict__ hist,
                           int* __restrict__ bsums, int n) {
    __shared__ int sh[256];
    int b = blockIdx.x, t = threadIdx.x;
    int base = b * 1024 + t * 4;
    int s = 0;
#pragma unroll
    for (int k = 0; k < 4; k++) { int i = base + k; if (i < n) s += hist[i]; }
    sh[t] = s; __syncthreads();
    for (int off = 128; off > 0; off >>= 1) {
        if (t < off) sh[t] += sh[t + off];
        __syncthreads();
    }
    if (t == 0) bsums[b] = sh[0];
}

__global__ void scan_offsets(const int* __restrict__ bsums,
                             int* __restrict__ boffs, int nb) {
    __shared__ int sh[256];
    int t = threadIdx.x;
    int v0 = (t < nb) ? bsums[t] : 0;
    sh[t] = v0; __syncthreads();
    for (int off = 1; off < 256; off <<= 1) {
        int u = (t >= off) ? sh[t - off] : 0;
        __syncthreads();
        sh[t] += u;
        __syncthreads();
    }
    boffs[t] = sh[t] - v0;   // exclusive
}

__global__ void scan_expand(const int* __restrict__ hist,
                            const int* __restrict__ boffs,
                            int* __restrict__ rowptr, int* __restrict__ cursor,
                            int n, int nE) {
    __shared__ int sh[256];
    int b = blockIdx.x, t = threadIdx.x;
    int base = b * 1024 + t * 4;
    int v[4]; int s = 0;
#pragma unroll
    for (int k = 0; k < 4; k++) {
        int i = base + k;
        v[k] = (i < n) ? hist[i] : 0;
        s += v[k];
    }
    sh[t] = s; __syncthreads();
    for (int off = 1; off < 256; off <<= 1) {
        int u = (t >= off) ? sh[t - off] : 0;
        __syncthreads();
        sh[t] += u;
        __syncthreads();
    }
    int off = boffs[b] + sh[t] - s;
#pragma unroll
    for (int k = 0; k < 4; k++) {
        int i = base + k;
        if (i < n) { rowptr[i] = off; cursor[i] = off; }
        off += v[k];
    }
    if (b == 0 && t == 0) rowptr[n] = nE;
}

__global__ void scatter_edges(const int* __restrict__ src,
                              const int* __restrict__ dst,
                              int* __restrict__ cursor,
                              int* __restrict__ esrc, int nE) {
    int e = blockIdx.x * blockDim.x + threadIdx.x;
    if (e < nE) {
        int p = atomicAdd(&cursor[dst[e]], 1);
        esrc[p] = src[e];
    }
}

// ---------------------------------------------------------------------------
// HMMA helpers
// ---------------------------------------------------------------------------
__device__ __forceinline__ void ldsm_x4(unsigned& r0, unsigned& r1,
                                        unsigned& r2, unsigned& r3,
                                        unsigned addr) {
    asm volatile("ldmatrix.sync.aligned.m8n8.x4.shared.b16 {%0,%1,%2,%3}, [%4];"
                 : "=r"(r0), "=r"(r1), "=r"(r2), "=r"(r3) : "r"(addr));
}
__device__ __forceinline__ void ldsm_x4_t(unsigned& r0, unsigned& r1,
                                          unsigned& r2, unsigned& r3,
                                          unsigned addr) {
    asm volatile("ldmatrix.sync.aligned.m8n8.x4.trans.shared.b16 {%0,%1,%2,%3}, [%4];"
                 : "=r"(r0), "=r"(r1), "=r"(r2), "=r"(r3) : "r"(addr));
}
__device__ __forceinline__ void mma16816(float* d, const unsigned* a,
                                         unsigned b0, unsigned b1) {
    asm volatile(
        "mma.sync.aligned.m16n8k16.row.col.f32.f16.f16.f32 "
        "{%0,%1,%2,%3}, {%4,%5,%6,%7}, {%8,%9}, {%0,%1,%2,%3};"
        : "+f"(d[0]), "+f"(d[1]), "+f"(d[2]), "+f"(d[3])
        : "r"(a[0]), "r"(a[1]), "r"(a[2]), "r"(a[3]), "r"(b0), "r"(b1));
}

// ---------------------------------------------------------------------------
// Fused HMMA GEMM: Y[r] = f(X[r]) @ W, K = N = 128, fp16 in / fp32 accum,
// Y stored fp16. Block = 256 thr, 64 rows x 128 cols. 8 warps: 4 row x 2 col.
// mode 0: f(x)[k] = x[k] * nsrc[r]
// mode 1: f(x)[k] = relu(x[k]*ndst[r] + bias[k]) * nsrc[r]
// ---------------------------------------------------------------------------
__global__ __launch_bounds__(256, 1) void gemm_mma(
    const float* __restrict__ X, const float* __restrict__ W,
    const float* __restrict__ bias, const float* __restrict__ nsrc,
    const float* __restrict__ ndst, __half* __restrict__ Y,
    int nRows, int mode)
{
    extern __shared__ __half sm[];
    __half* Ws = sm;                        // 128 x WS_STRIDE
    __half* Xs = sm + D * WS_STRIDE;        // 64 x XS_STRIDE
    const int tid = threadIdx.x;
    const int row0 = blockIdx.x * 64;

    // W (fp32 global) -> fp16 smem
    {
        const float4* Wg = (const float4*)W;
#pragma unroll
        for (int i = 0; i < 16; i++) {
            int idx = tid + i * 256;        // float4 idx, 4096 total
            float4 v = Wg[idx];
            int r = idx >> 5;               // 32 float4 per row
            int c = (idx & 31) * 4;
            __half2 h0 = __floats2half2_rn(v.x, v.y);
            __half2 h1 = __floats2half2_rn(v.z, v.w);
            uint2 p;
            p.x = *(unsigned*)&h0; p.y = *(unsigned*)&h1;
            *(uint2*)&Ws[r * WS_STRIDE + c] = p;
        }
    }
    // X tile: load fp32, transform, pack fp16
    {
#pragma unroll
        for (int i = 0; i < 8; i++) {
            int linear = tid + i * 256;     // 2048 = 64 rows * 32 float4
            int row = linear >> 5;
            int c4  = linear & 31;
            int gr  = row0 + row;
            float4 v = make_float4(0.f, 0.f, 0.f, 0.f);
            if (gr < nRows) {
                v = ((const float4*)(X + (size_t)gr * D))[c4];
                if (mode == 0) {
                    float s = nsrc[gr];
                    v.x *= s; v.y *= s; v.z *= s; v.w *= s;
                } else {
                    float a = ndst[gr];
                    float s = nsrc[gr];
                    float4 bb = ((const float4*)bias)[c4];
                    v.x = fmaxf(fmaf(v.x, a, bb.x), 0.f) * s;
                    v.y = fmaxf(fmaf(v.y, a, bb.y), 0.f) * s;
                    v.z = fmaxf(fmaf(v.z, a, bb.z), 0.f) * s;
                    v.w = fmaxf(fmaf(v.w, a, bb.w), 0.f) * s;
                }
            }
            __half2 h0 = __floats2half2_rn(v.x, v.y);
            __half2 h1 = __floats2half2_rn(v.z, v.w);
            uint2 p;
            p.x = *(unsigned*)&h0; p.y = *(unsigned*)&h1;
            *(uint2*)&Xs[row * XS_STRIDE + c4 * 4] = p;
        }
    }
    __syncthreads();

    const int warp = tid >> 5;
    const int lane = tid & 31;
    const int m0 = (warp & 3) * 16;         // warp row offset in tile
    const int n0 = (warp >> 2) * 64;        // warp col offset

    float acc[8][4];
#pragma unroll
    for (int i = 0; i < 8; i++)
#pragma unroll
        for (int j = 0; j < 4; j++) acc[i][j] = 0.f;

    // ldmatrix base addresses (byte offsets in shared space)
    unsigned xs_base = (unsigned)__cvta_generic_to_shared(
        &Xs[(m0 + (lane & 15)) * XS_STRIDE]) + (lane >> 4) * 16;
    unsigned ws_base = (unsigned)__cvta_generic_to_shared(
        &Ws[(lane & 15) * WS_STRIDE + n0]) + (lane >> 4) * 16;

#pragma unroll
    for (int k = 0; k < D; k += 16) {
        unsigned a[4];
        ldsm_x4(a[0], a[1], a[2], a[3], xs_base + k * 2);
        unsigned wrow = ws_base + k * (WS_STRIDE * 2);
#pragma unroll
        for (int q = 0; q < 4; q++) {       // 4 x (16-wide) = 64 cols
            unsigned b0, b1, b2, b3;
            ldsm_x4_t(b0, b1, b2, b3, wrow + q * 32);
            mma16816(acc[q * 2],     a, b0, b1);
            mma16816(acc[q * 2 + 1], a, b2, b3);
        }
    }

    // store: c layout m16n8 -> thread holds (row=lane/4, col=2*(lane%3..)):
    int r0 = row0 + m0 + (lane >> 2);
    int cb = n0 + (lane & 3) * 2;
#pragma unroll
    for (int nt = 0; nt < 8; nt++) {
        int c = cb + nt * 8;
        if (r0 < nRows) {
            __half2 h = __floats2half2_rn(acc[nt][0], acc[nt][1]);
            *(__half2*)(Y + (size_t)r0 * D + c) = h;
        }
        if (r0 + 8 < nRows) {
            __half2 h = __floats2half2_rn(acc[nt][2], acc[nt][3]);
            *(__half2*)(Y + (size_t)(r0 + 8) * D + c) = h;
        }
    }
}

// ---------------------------------------------------------------------------
// CSR SpMM gather-reduce (fp16 t): one warp per dst node.
// MODE 0: out[node] = sum t[src[e]]                 (fp32 raw agg)
// MODE 1: out[node] = relu(sum * nd[node] + bias)   (final h, fp32)
// ---------------------------------------------------------------------------
template<int MODE>
__global__ __launch_bounds__(256) void csr_spmm(
    const __half* __restrict__ t, const int* __restrict__ rowptr,
    const int* __restrict__ esrc, const float* __restrict__ nd,
    const float* __restrict__ bias, float* __restrict__ out, int nNodes)
{
    int node = blockIdx.x * 8 + (threadIdx.x >> 5);
    if (node >= nNodes) return;
    int lane = threadIdx.x & 31;
    int beg = rowptr[node];
    int end = rowptr[node + 1];

    float4 a0 = make_float4(0.f, 0.f, 0.f, 0.f);
    float4 a1 = make_float4(0.f, 0.f, 0.f, 0.f);
    float4 a2 = make_float4(0.f, 0.f, 0.f, 0.f);
    float4 a3 = make_float4(0.f, 0.f, 0.f, 0.f);

#define ACCUM(ACC, U)                                                     \
    {                                                                     \
        float2 f0 = __half22float2(*(const __half2*)&(U).x);              \
        float2 f1 = __half22float2(*(const __half2*)&(U).y);              \
        (ACC).x += f0.x; (ACC).y += f0.y; (ACC).z += f1.x; (ACC).w += f1.y;\
    }

    int j = beg;
    for (; j + 3 < end; j += 4) {
        int s0 = esrc[j], s1 = esrc[j + 1], s2 = esrc[j + 2], s3 = esrc[j + 3];
        uint2 v0 = __ldg((const uint2*)(t + (size_t)s0 * D) + lane);
        uint2 v1 = __ldg((const uint2*)(t + (size_t)s1 * D) + lane);
        uint2 v2 = __ldg((const uint2*)(t + (size_t)s2 * D) + lane);
        uint2 v3 = __ldg((const uint2*)(t + (size_t)s3 * D) + lane);
        ACCUM(a0, v0); ACCUM(a1, v1); ACCUM(a2, v2); ACCUM(a3, v3);
    }
    for (; j < end; j++) {
        int s = esrc[j];
        uint2 v = __ldg((const uint2*)(t + (size_t)s * D) + lane);
        ACCUM(a0, v);
    }
#undef ACCUM

    float4 acc;
    acc.x = (a0.x + a1.x) + (a2.x + a3.x);
    acc.y = (a0.y + a1.y) + (a2.y + a3.y);
    acc.z = (a0.z + a1.z) + (a2.z + a3.z);
    acc.w = (a0.w + a1.w) + (a2.w + a3.w);

    if (MODE == 1) {
        float a = nd[node];
        float4 bb = __ldg((const float4*)bias + lane);
        acc.x = fmaxf(fmaf(acc.x, a, bb.x), 0.f);
        acc.y = fmaxf(fmaf(acc.y, a, bb.y), 0.f);
        acc.z = fmaxf(fmaf(acc.z, a, bb.z), 0.f);
        acc.w = fmaxf(fmaf(acc.w, a, bb.w), 0.f);
    }
    *(float4*)(out + (size_t)node * D + lane * 4) = acc;
}

// ---------------------------------------------------------------------------
__device__ __forceinline__ int lower_bound_i(const int* a, int n, int v) {
    int lo = 0, hi = n;
    while (lo < hi) {
        int mid = (lo + hi) >> 1;
        if (a[mid] < v) lo = mid + 1; else hi = mid;
    }
    return lo;
}

__global__ void pool_kernel(const float* __restrict__ h,
                            const int* __restrict__ gid,
                            int nNodes, float* __restrict__ hg) {
    int g = blockIdx.x;
    int t = threadIdx.x;
    int lo = lower_bound_i(gid, nNodes, g);
    int hi = lower_bound_i(gid, nNodes, g + 1);
    float s0 = 0.f, s1 = 0.f, s2 = 0.f, s3 = 0.f;
    int r = lo;
    for (; r + 3 < hi; r += 4) {
        s0 += h[(size_t)r * D + t];
        s1 += h[(size_t)(r + 1) * D + t];
        s2 += h[(size_t)(r + 2) * D + t];
        s3 += h[(size_t)(r + 3) * D + t];
    }
    for (; r < hi; r++) s0 += h[(size_t)r * D + t];
    float cnt = (float)(hi - lo);
    hg[g * D + t] = ((s0 + s1) + (s2 + s3)) / fmaxf(cnt, 1.0f);
}

__global__ void readout_kernel(const float* __restrict__ in,
                               const float* __restrict__ W,
                               const float* __restrict__ b,
                               float* __restrict__ out, int doRelu) {
    __shared__ float row[D];
    int g = blockIdx.x, t = threadIdx.x;
    row[t] = in[g * D + t];
    __syncthreads();
    float acc = b[t];
#pragma unroll 8
    for (int k = 0; k < D; k++) acc = fmaf(row[k], W[k * D + t], acc);
    if (doRelu) acc = fmaxf(acc, 0.f);
    out[g * D + t] = acc;
}

// ---------------------------------------------------------------------------
extern "C" void kernel_launch(void* const* d_in, const int* in_sizes, int n_in,
                              void* d_out, int out_size) {
    const float* x   = (const float*)d_in[0];
    const int*   ei  = (const int*)d_in[1];
    const int*   gid = (const int*)d_in[2];
    int wbase = (n_in >= 12) ? 4 : 3;
    const float* W1  = (const float*)d_in[wbase + 0];
    const float* b1  = (const float*)d_in[wbase + 1];
    const float* W2  = (const float*)d_in[wbase + 2];
    const float* b2  = (const float*)d_in[wbase + 3];
    const float* Wr1 = (const float*)d_in[wbase + 4];
    const float* br1 = (const float*)d_in[wbase + 5];
    const float* Wr2 = (const float*)d_in[wbase + 6];
    const float* br2 = (const float*)d_in[wbase + 7];

    const int nNodes = in_sizes[0] / D;
    const int nE     = in_sizes[1] / 2;
    const int* src = ei;
    const int* dst = ei + nE;

    float* out_g = (float*)d_out;
    float* out_h = out_g + 64 * D;

    int    *hist, *rowptr, *cursor, *esrc, *bsums, *boffs;
    float  *nrm, *agg, *hg, *tmp;
    __half *t;
    cudaGetSymbolAddress((void**)&hist,   g_hist);
    cudaGetSymbolAddress((void**)&rowptr, g_rowptr);
    cudaGetSymbolAddress((void**)&cursor, g_cursor);
    cudaGetSymbolAddress((void**)&esrc,   g_esrc);
    cudaGetSymbolAddress((void**)&bsums,  g_bsums);
    cudaGetSymbolAddress((void**)&boffs,  g_boffs);
    cudaGetSymbolAddress((void**)&nrm,    g_norm);
    cudaGetSymbolAddress((void**)&t,      g_t);
    cudaGetSymbolAddress((void**)&agg,    g_agg);
    cudaGetSymbolAddress((void**)&hg,     g_hg);
    cudaGetSymbolAddress((void**)&tmp,    g_tmp);

    int* hdst = hist;
    int* hsrc = hist + MAX_NODES;
    float* ns = nrm;
    float* nd = nrm + MAX_NODES;

    const int smemGemm = (D * WS_STRIDE + 64 * XS_STRIDE) * (int)sizeof(__half);
    cudaFuncSetAttribute(gemm_mma, cudaFuncAttributeMaxDynamicSharedMemorySize,
                         smemGemm);

    const int nb = (nNodes + 1023) / 1024;

    // CSR build + norms
    cudaMemsetAsync(hist, 0, 2 * (size_t)MAX_NODES * sizeof(int), 0);
    hist_kernel<<<(nE + 255) / 256, 256>>>(src, dst, hdst, hsrc, nE);
    norm_kernel<<<(nNodes + 255) / 256, 256>>>(hsrc, hdst, ns, nd, nNodes);
    scan_bsums<<<nb, 256>>>(hdst, bsums, nNodes);
    scan_offsets<<<1, 256>>>(bsums, boffs, nb);
    scan_expand<<<nb, 256>>>(hdst, boffs, rowptr, cursor, nNodes, nE);
    scatter_edges<<<(nE + 255) / 256, 256>>>(src, dst, cursor, esrc, nE);

    int gemmBlocks = (nNodes + 63) / 64;
    int spmmBlocks = (nNodes + 7) / 8;

    // layer 1
    gemm_mma<<<gemmBlocks, 256, smemGemm>>>(x, W1, nullptr, ns, nullptr, t,
                                            nNodes, 0);
    csr_spmm<0><<<spmmBlocks, 256>>>(t, rowptr, esrc, nullptr, nullptr, agg,
                                     nNodes);

    // layer 2 (epilogue fused: writes h directly into d_out)
    gemm_mma<<<gemmBlocks, 256, smemGemm>>>(agg, W2, b1, ns, nd, t,
                                            nNodes, 1);
    csr_spmm<1><<<spmmBlocks, 256>>>(t, rowptr, esrc, nd, b2, out_h, nNodes);

    // pooling + readout MLP
    pool_kernel<<<64, D>>>(out_h, gid, nNodes, hg);
    readout_kernel<<<64, D>>>(hg, Wr1, br1, tmp, 1);
    readout_kernel<<<64, D>>>(tmp, Wr2, br2, out_g, 0);
}